// round 1
// baseline (speedup 1.0000x reference)
#include <cuda_runtime.h>
#include <math.h>

#define N_USERS 60000
#define N_ITEMS 40000
#define NU      60001            /* N_USERS + 1 */
#define NND     100002           /* total nodes */
#define D       64
#define ND64    (NND * 64)       /* 6,400,128 */
#define E_GLOBAL 1000000
#define E_BEH    500000
#define BATCH    4096

/* ---------------- scratch (device globals — allowed) ---------------- */
__device__ float g_h[ND64];
__device__ float g_hw[ND64];
__device__ float g_out[ND64];
__device__ float g_base[ND64];
__device__ float g_beh[3][ND64];
__device__ float g_w[3][ND64];
__device__ float g_dinv[4 * NND];
__device__ float g_sc[2];

/* ---------------- helpers ---------------- */
__device__ __forceinline__ float warp_sum(float v) {
#pragma unroll
    for (int o = 16; o; o >>= 1) v += __shfl_xor_sync(0xffffffffu, v, o);
    return v;
}

/* ---------------- zero everything that needs zeroing ---------------- */
__global__ void zero_k(float* out) {
    int i = blockIdx.x * blockDim.x + threadIdx.x;
    if (i < ND64) g_out[i] = 0.0f;
    if (i < 4 * NND) g_dinv[i] = 0.0f;
    if (i < 2) g_sc[i] = 0.0f;
    if (i == 0) out[0] = 0.0f;
}

/* ---------------- concat user/item emb into g_h and g_base ---------------- */
__global__ void concat_k(const float* __restrict__ ue, const float* __restrict__ ie) {
    int t = blockIdx.x * blockDim.x + threadIdx.x;   /* one float4 each */
    if (t >= NND * 16) return;
    int node = t >> 4, q = t & 15;
    float4 v = (node < NU) ? ((const float4*)ue)[node * 16 + q]
                           : ((const float4*)ie)[(node - NU) * 16 + q];
    ((float4*)g_h)[t]    = v;
    ((float4*)g_base)[t] = v;
}

/* ---------------- sum of squares (for emb_loss) ---------------- */
__global__ void sumsq_k(const float* __restrict__ x, int n4, int sel) {
    float s = 0.0f;
    for (int i = blockIdx.x * blockDim.x + threadIdx.x; i < n4;
         i += gridDim.x * blockDim.x) {
        float4 v = ((const float4*)x)[i];
        s += v.x * v.x + v.y * v.y + v.z * v.z + v.w * v.w;
    }
    __shared__ float sm[256];
    sm[threadIdx.x] = s;
    __syncthreads();
    for (int o = 128; o; o >>= 1) {
        if (threadIdx.x < o) sm[threadIdx.x] += sm[threadIdx.x + o];
        __syncthreads();
    }
    if (threadIdx.x == 0) atomicAdd(&g_sc[sel], sm[0]);
}

/* ---------------- degree count / dinv ---------------- */
__global__ void degcnt_k(const int* __restrict__ dst, int E, int sel) {
    int i = blockIdx.x * blockDim.x + threadIdx.x;
    if (i < E) atomicAdd(&g_dinv[sel * NND + dst[i]], 1.0f);
}
__global__ void dinv_k() {
    int i = blockIdx.x * blockDim.x + threadIdx.x;
    if (i < 4 * NND) {
        float d = g_dinv[i];
        g_dinv[i] = (d > 0.0f) ? rsqrtf(d) : 0.0f;
    }
}

/* ---------------- GEMM: g_hw = g_h @ W   (N x 64 @ 64 x 64) ---------------- */
__global__ __launch_bounds__(256) void gemm_k(const float* __restrict__ W) {
    __shared__ float sW[64 * 64];
    __shared__ float sAT[64 * 64];   /* transposed tile: sAT[k*64 + r] */
    int tid  = threadIdx.x;
    int row0 = blockIdx.x * 64;

    const float4* W4  = (const float4*)W;
    float4*       sW4 = (float4*)sW;
#pragma unroll
    for (int i = tid; i < 1024; i += 256) sW4[i] = W4[i];

#pragma unroll
    for (int i = tid; i < 1024; i += 256) {
        int r = i >> 4, kq = i & 15;
        int row = row0 + r;
        float4 v = make_float4(0.f, 0.f, 0.f, 0.f);
        if (row < NND) v = ((const float4*)g_h)[row * 16 + kq];
        int k = kq * 4;
        sAT[(k + 0) * 64 + r] = v.x;
        sAT[(k + 1) * 64 + r] = v.y;
        sAT[(k + 2) * 64 + r] = v.z;
        sAT[(k + 3) * 64 + r] = v.w;
    }
    __syncthreads();

    int tx = tid & 15, ty = tid >> 4;
    int c0 = tx * 4, r0 = ty * 4;
    float acc[4][4] = {};
#pragma unroll 16
    for (int k = 0; k < 64; k++) {
        float4 a = *(const float4*)&sAT[k * 64 + r0];
        float4 w = *(const float4*)&sW[k * 64 + c0];
        acc[0][0] += a.x * w.x; acc[0][1] += a.x * w.y; acc[0][2] += a.x * w.z; acc[0][3] += a.x * w.w;
        acc[1][0] += a.y * w.x; acc[1][1] += a.y * w.y; acc[1][2] += a.y * w.z; acc[1][3] += a.y * w.w;
        acc[2][0] += a.z * w.x; acc[2][1] += a.z * w.y; acc[2][2] += a.z * w.z; acc[2][3] += a.z * w.w;
        acc[3][0] += a.w * w.x; acc[3][1] += a.w * w.y; acc[3][2] += a.w * w.z; acc[3][3] += a.w * w.w;
    }
#pragma unroll
    for (int i = 0; i < 4; i++) {
        int row = row0 + r0 + i;
        if (row < NND) {
            float4 o = make_float4(acc[i][0], acc[i][1], acc[i][2], acc[i][3]);
            ((float4*)g_hw)[row * 16 + (c0 >> 2)] = o;
        }
    }
}

/* ---------------- scatter: g_out[dst] += g_hw[src] * dinv[src]*dinv[dst] -------- */
__global__ void scatter_k(const int* __restrict__ src, const int* __restrict__ dst,
                          int E, int dsel) {
    int t = blockIdx.x * blockDim.x + threadIdx.x;
    int e = t >> 4;                 /* 16 threads (one float4 each) per edge */
    int q = t & 15;
    if (e >= E) return;
    int s = src[e], d = dst[e];
    const float* dv = &g_dinv[dsel * NND];
    float c = dv[s] * dv[d];
    if (c == 0.0f) return;
    float4 v = ((const float4*)g_hw)[s * 16 + q];
    float4* o = ((float4*)g_out) + d * 16 + q;
    asm volatile("red.global.add.v4.f32 [%0], {%1,%2,%3,%4};"
                 :: "l"(o), "f"(v.x * c), "f"(v.y * c), "f"(v.z * c), "f"(v.w * c)
                 : "memory");
}

/* ---------------- finish: +b, L2-normalize, h update, res accumulate ---------- */
__global__ void finish_k(const float* __restrict__ b, float invL, int res_sel) {
    int t = blockIdx.x * blockDim.x + threadIdx.x;
    int node = t >> 5, lane = t & 31;
    if (node >= NND) return;
    float2 bv = ((const float2*)b)[lane];
    float2 v  = ((float2*)g_out)[node * 32 + lane];
    ((float2*)g_out)[node * 32 + lane] = make_float2(0.f, 0.f);  /* re-zero for next layer */
    v.x += bv.x; v.y += bv.y;
    float ss  = warp_sum(v.x * v.x + v.y * v.y);
    float nrm = fmaxf(sqrtf(ss), 1e-12f);
    float inv = 1.0f / nrm;
    float2 h  = make_float2(v.x * inv, v.y * inv);
    ((float2*)g_h)[node * 32 + lane] = h;
    float* res = (res_sel < 0) ? g_base : g_beh[res_sel];
    float2 r = ((float2*)res)[node * 32 + lane];
    r.x += h.x * invL; r.y += h.y * invL;
    ((float2*)res)[node * 32 + lane] = r;
}

/* ---------------- per-behavior encoder init: h = base, res = base -------------- */
__global__ void copyinit_k(int b) {
    int i = blockIdx.x * blockDim.x + threadIdx.x;
    if (i >= NND * 16) return;
    float4 v = ((const float4*)g_base)[i];
    ((float4*)g_h)[i]        = v;
    ((float4*)g_beh[b])[i]   = v;
}

/* ---------------- mutual attention + global/beh weighted combine --------------- */
__global__ void attn_k() {
    int t = blockIdx.x * blockDim.x + threadIdx.x;
    int node = t >> 5, lane = t & 31;
    if (node >= NND) return;
    int off = node * 32 + lane;
    float2 t0 = ((const float2*)g_beh[0])[off];
    float2 t1 = ((const float2*)g_beh[1])[off];
    float2 t2 = ((const float2*)g_beh[2])[off];

    float s00 = warp_sum(t0.x * t0.x + t0.y * t0.y);
    float s01 = warp_sum(t0.x * t1.x + t0.y * t1.y);
    float s02 = warp_sum(t0.x * t2.x + t0.y * t2.y);
    float s11 = warp_sum(t1.x * t1.x + t1.y * t1.y);
    float s12 = warp_sum(t1.x * t2.x + t1.y * t2.y);
    float s22 = warp_sum(t2.x * t2.x + t2.y * t2.y);

    const float sc = 0.125f;   /* 1/sqrt(64) */
    float s[3][3] = {{s00 * sc, s01 * sc, s02 * sc},
                     {s01 * sc, s11 * sc, s12 * sc},
                     {s02 * sc, s12 * sc, s22 * sc}};

    bool isU = node < NU;
    float gw = isU ? 2.35f : 1.0f;
    float bw = isU ? 0.242f : 0.55f;
    float2 gv = ((const float2*)g_base)[off];

#pragma unroll
    for (int b = 0; b < 3; b++) {
        float m  = fmaxf(s[b][0], fmaxf(s[b][1], s[b][2]));
        float e0 = __expf(s[b][0] - m), e1 = __expf(s[b][1] - m), e2 = __expf(s[b][2] - m);
        float is = 1.0f / (e0 + e1 + e2);
        float a0 = e0 * is, a1 = e1 * is, a2 = e2 * is;
        float2 o = make_float2(a0 * t0.x + a1 * t1.x + a2 * t2.x,
                               a0 * t0.y + a1 * t1.y + a2 * t2.y);
        ((float2*)g_w[b])[off] = make_float2(gw * gv.x + bw * o.x,
                                             gw * gv.y + bw * o.y);
    }
}

/* ---------------- BPR loss over batch: 9 (i,j) pairs -------------------------- */
__global__ void loss_k(const int* __restrict__ bd, float* out) {
    int t = blockIdx.x * blockDim.x + threadIdx.x;
    int w = t >> 5, lane = t & 31;
    float partial = 0.0f;
    if (w < BATCH * 9) {
        int k = w / 9, pr = w - k * 9;
        int i = pr / 3, j = pr - i * 3;
        int u  = bd[k * 9 + i * 3 + 0];
        int ip = bd[k * 9 + i * 3 + 1];
        int in_ = bd[k * 9 + i * 3 + 2];
        float2 uu = ((const float2*)g_w[i])[u * 32 + lane];
        float2 pp = ((const float2*)g_w[j])[(NU + ip) * 32 + lane];
        float2 nn = ((const float2*)g_w[j])[(NU + in_) * 32 + lane];
        float sp = warp_sum(uu.x * pp.x + uu.y * pp.y);
        float sn = warp_sum(uu.x * nn.x + uu.y * nn.y);
        float x  = sp - sn;
        float ls = fminf(x, 0.0f) - log1pf(expf(-fabsf(x)));
        partial = -ls * (1.0f / (float)BATCH);
    }
    __shared__ float sm[8];
    if (lane == 0) sm[threadIdx.x >> 5] = partial;
    __syncthreads();
    if (threadIdx.x == 0) {
        float s = 0.0f;
#pragma unroll
        for (int q = 0; q < 8; q++) s += sm[q];
        atomicAdd(out, s);
    }
}

/* ---------------- finalize: add regularizer ---------------- */
__global__ void final_k(float* out) {
    out[0] += 0.001f * ((sqrtf(g_sc[0]) + sqrtf(g_sc[1])) / (float)(N_ITEMS + 1));
}

/* ================================ launch ================================ */
extern "C" void kernel_launch(void* const* d_in, const int* in_sizes, int n_in,
                              void* d_out, int out_size) {
    const float* ue  = (const float*)d_in[0];
    const float* ie  = (const float*)d_in[1];
    const float* gW  = (const float*)d_in[2];
    const float* gb  = (const float*)d_in[3];
    const float* bW  = (const float*)d_in[4];
    const float* bb  = (const float*)d_in[5];
    const int*   aei = (const int*)d_in[6];
    const int*   bei = (const int*)d_in[7];
    const int*   bd  = (const int*)d_in[8];
    float* out = (float*)d_out;

    const int T = 256;
    dim3 blk(T);

    /* zeroing + init */
    zero_k<<<(ND64 + T - 1) / T, blk>>>(out);
    concat_k<<<(NND * 16 + T - 1) / T, blk>>>(ue, ie);
    sumsq_k<<<256, blk>>>(ue, NU * 16, 0);
    sumsq_k<<<256, blk>>>(ie, (N_ITEMS + 1) * 16, 1);

    /* degrees (once per graph) */
    degcnt_k<<<(E_GLOBAL + T - 1) / T, blk>>>(aei + E_GLOBAL, E_GLOBAL, 0);
    for (int b = 0; b < 3; b++)
        degcnt_k<<<(E_BEH + T - 1) / T, blk>>>(bei + (b * 2 + 1) * E_BEH, E_BEH, 1 + b);
    dinv_k<<<(4 * NND + T - 1) / T, blk>>>();

    const int GEMM_BLOCKS = (NND + 63) / 64;
    const int FIN_BLOCKS  = (NND * 32 + T - 1) / T;

    /* global encoder: 2 layers */
    for (int l = 0; l < 2; l++) {
        gemm_k<<<GEMM_BLOCKS, blk>>>(gW + l * 4096);
        scatter_k<<<((long)E_GLOBAL * 16 + T - 1) / T, blk>>>(aei, aei + E_GLOBAL, E_GLOBAL, 0);
        finish_k<<<FIN_BLOCKS, blk>>>(gb + l * 64, 1.0f / (float)(l + 1), -1);
    }

    /* behavioral encoders: 3 x 2 layers */
    for (int b = 0; b < 3; b++) {
        copyinit_k<<<(NND * 16 + T - 1) / T, blk>>>(b);
        const int* bsrc = bei + b * 2 * E_BEH;
        const int* bdst = bsrc + E_BEH;
        for (int l = 0; l < 2; l++) {
            gemm_k<<<GEMM_BLOCKS, blk>>>(bW + (b * 2 + l) * 4096);
            scatter_k<<<((long)E_BEH * 16 + T - 1) / T, blk>>>(bsrc, bdst, E_BEH, 1 + b);
            finish_k<<<FIN_BLOCKS, blk>>>(bb + (b * 2 + l) * 64, 1.0f / (float)(l + 1), b);
        }
    }

    /* attention + combine, then loss */
    attn_k<<<FIN_BLOCKS, blk>>>();
    loss_k<<<(BATCH * 9 * 32 + T - 1) / T, blk>>>(bd, out);
    final_k<<<1, 1>>>(out);
}

// round 3
// speedup vs baseline: 2.3013x; 2.3013x over previous
#include <cuda_runtime.h>
#include <math.h>

#define N_USERS 60000
#define N_ITEMS 40000
#define NU      60001            /* N_USERS + 1 */
#define NND     100002           /* total nodes */
#define D       64
#define ND64    (NND * 64)
#define E_GLOBAL 1000000
#define E_BEH    500000
#define E_TOT   (E_GLOBAL + 3 * E_BEH)
#define BATCH    4096

#define SCB 512
#define NCH ((NND + SCB - 1) / SCB)      /* chunks per graph */

/* ---------------- scratch (device globals) ---------------- */
__device__ float g_h[ND64];
__device__ float g_hw[ND64];
__device__ float g_base[ND64];
__device__ float g_beh[3][ND64];
__device__ float g_w[3][ND64];
__device__ float g_dinv[4 * NND];
__device__ int   g_deg[4 * NND];
__device__ int   g_part[4 * NCH];
__device__ int   g_ptr[4 * (NND + 1)];
__device__ int   g_cnt[4 * NND];
__device__ int   g_csr[E_TOT];
__device__ float g_sc[2];

/* ---------------- helpers ---------------- */
__device__ __forceinline__ float warp_sum(float v) {
#pragma unroll
    for (int o = 16; o; o >>= 1) v += __shfl_xor_sync(0xffffffffu, v, o);
    return v;
}

#define FMA2(d, a, b) asm("fma.rn.f32x2 %0, %1, %2, %0;" : "+l"(d) : "l"(a), "l"(b))
#define PACK2(p, f)   asm("mov.b64 %0, {%1, %1};" : "=l"(p) : "r"(__float_as_uint(f)))

/* ---------------- zero ---------------- */
__global__ void zero_k(float* out) {
    int i = blockIdx.x * blockDim.x + threadIdx.x;
    if (i < 4 * NND) g_deg[i] = 0;
    if (i < 2) g_sc[i] = 0.0f;
    if (i == 0) out[0] = 0.0f;
}

/* ---------------- concat user/item emb into g_h and g_base ---------------- */
__global__ void concat_k(const float* __restrict__ ue, const float* __restrict__ ie) {
    int t = blockIdx.x * blockDim.x + threadIdx.x;
    if (t >= NND * 16) return;
    int node = t >> 4, q = t & 15;
    float4 v = (node < NU) ? ((const float4*)ue)[node * 16 + q]
                           : ((const float4*)ie)[(node - NU) * 16 + q];
    ((float4*)g_base)[t] = v;
}

/* ---------------- sum of squares ---------------- */
__global__ void sumsq_k(const float* __restrict__ x, int n4, int sel) {
    float s = 0.0f;
    for (int i = blockIdx.x * blockDim.x + threadIdx.x; i < n4;
         i += gridDim.x * blockDim.x) {
        float4 v = ((const float4*)x)[i];
        s += v.x * v.x + v.y * v.y + v.z * v.z + v.w * v.w;
    }
    __shared__ float sm[256];
    sm[threadIdx.x] = s;
    __syncthreads();
    for (int o = 128; o; o >>= 1) {
        if (threadIdx.x < o) sm[threadIdx.x] += sm[threadIdx.x + o];
        __syncthreads();
    }
    if (threadIdx.x == 0) atomicAdd(&g_sc[sel], sm[0]);
}

/* ---------------- degree count / dinv ---------------- */
__global__ void degcnt_k(const int* __restrict__ dst, int E, int g) {
    int i = blockIdx.x * blockDim.x + threadIdx.x;
    if (i < E) atomicAdd(&g_deg[g * NND + dst[i]], 1);
}
__global__ void dinv_k() {
    int i = blockIdx.x * blockDim.x + threadIdx.x;
    if (i < 4 * NND) {
        int d = g_deg[i];
        g_dinv[i] = (d > 0) ? rsqrtf((float)d) : 0.0f;
    }
}

/* ---------------- CSR build: chunk partials, scan, fill ---------------- */
__global__ __launch_bounds__(SCB) void part_k() {
    __shared__ int sm[SCB];
    int b = blockIdx.x;
    int g = b / NCH, ch = b % NCH;
    int idx = ch * SCB + threadIdx.x;
    int v = (idx < NND) ? g_deg[g * NND + idx] : 0;
    sm[threadIdx.x] = v;
    __syncthreads();
    for (int o = SCB / 2; o; o >>= 1) {
        if (threadIdx.x < o) sm[threadIdx.x] += sm[threadIdx.x + o];
        __syncthreads();
    }
    if (threadIdx.x == 0) g_part[b] = sm[0];
}

__global__ void scanpart_k() {
    int g = threadIdx.x;
    if (g >= 4) return;
    int run = 0;
    for (int c = 0; c < NCH; c++) {
        int v = g_part[g * NCH + c];
        g_part[g * NCH + c] = run;
        run += v;
    }
    g_ptr[g * (NND + 1) + NND] = run;
}

__global__ __launch_bounds__(SCB) void scan_k() {
    __shared__ int sm[SCB];
    int b = blockIdx.x;
    int g = b / NCH, ch = b % NCH;
    int idx = ch * SCB + threadIdx.x;
    int v = (idx < NND) ? g_deg[g * NND + idx] : 0;
    sm[threadIdx.x] = v;
    __syncthreads();
    for (int o = 1; o < SCB; o <<= 1) {
        int add = (threadIdx.x >= o) ? sm[threadIdx.x - o] : 0;
        __syncthreads();
        sm[threadIdx.x] += add;
        __syncthreads();
    }
    int excl = sm[threadIdx.x] - v + g_part[b];
    if (idx < NND) {
        g_ptr[g * (NND + 1) + idx] = excl;
        g_cnt[g * NND + idx]       = excl;
    }
}

__global__ void fill_k(const int* __restrict__ src, const int* __restrict__ dst,
                       int E, int g, int base) {
    int i = blockIdx.x * blockDim.x + threadIdx.x;
    if (i >= E) return;
    int d = dst[i];
    int pos = atomicAdd(&g_cnt[g * NND + d], 1);
    g_csr[base + pos] = src[i];
}

/* ---------------- GEMM: g_hw = A @ W  (srcsel: 0=g_base, 1=g_h) ---------------- */
__global__ __launch_bounds__(128) void gemm_k(const float* __restrict__ W, int srcsel) {
    __shared__ float sA[64 * 65];
    __shared__ float sW[64 * 64];
    int tid  = threadIdx.x;
    int row0 = blockIdx.x * 64;
    const float* A = srcsel ? g_h : g_base;   /* device-side symbol resolution */

#pragma unroll
    for (int i = tid; i < 1024; i += 128) ((float4*)sW)[i] = ((const float4*)W)[i];
#pragma unroll
    for (int i = tid; i < 1024; i += 128) {
        int r = i >> 4, kq = i & 15;
        int row = row0 + r;
        float4 v = make_float4(0.f, 0.f, 0.f, 0.f);
        if (row < NND) v = ((const float4*)A)[row * 16 + kq];
        int base = r * 65 + kq * 4;
        sA[base + 0] = v.x; sA[base + 1] = v.y;
        sA[base + 2] = v.z; sA[base + 3] = v.w;
    }
    __syncthreads();

    int tx = tid & 7, ty = tid >> 3;
    int c0 = tx * 4, c1 = 32 + tx * 4, r0 = ty * 4;

    unsigned long long acc[4][4] = {};
    const unsigned long long* sW64 = (const unsigned long long*)sW;

#pragma unroll 8
    for (int k = 0; k < 64; k++) {
        unsigned long long w0 = sW64[(k * 64 + c0) >> 1];
        unsigned long long w1 = sW64[(k * 64 + c0 + 2) >> 1];
        unsigned long long w2 = sW64[(k * 64 + c1) >> 1];
        unsigned long long w3 = sW64[(k * 64 + c1 + 2) >> 1];
#pragma unroll
        for (int i = 0; i < 4; i++) {
            float a = sA[(r0 + i) * 65 + k];
            unsigned long long a2;
            PACK2(a2, a);
            FMA2(acc[i][0], a2, w0);
            FMA2(acc[i][1], a2, w1);
            FMA2(acc[i][2], a2, w2);
            FMA2(acc[i][3], a2, w3);
        }
    }

#pragma unroll
    for (int i = 0; i < 4; i++) {
        int row = row0 + r0 + i;
        if (row >= NND) break;
        float2 p0 = *(float2*)&acc[i][0];
        float2 p1 = *(float2*)&acc[i][1];
        float2 p2 = *(float2*)&acc[i][2];
        float2 p3 = *(float2*)&acc[i][3];
        ((float4*)g_hw)[row * 16 + tx]     = make_float4(p0.x, p0.y, p1.x, p1.y);
        ((float4*)g_hw)[row * 16 + 8 + tx] = make_float4(p2.x, p2.y, p3.x, p3.y);
    }
}

/* ------- gather + finish: out = dinv[d]*Σ dinv[s]*hw[s] + b, norm, res ------- */
__global__ void gather_k(int csr_base, int g, const float* __restrict__ bias,
                         float invL, int res_sel, int add_base, int write_h) {
    int t = blockIdx.x * blockDim.x + threadIdx.x;
    int node = t >> 5, lane = t & 31;
    if (node >= NND) return;
    const int* ptr = g_ptr + g * (NND + 1);
    const int* csr = g_csr + csr_base;
    const float* dv = g_dinv + g * NND;
    int beg = ptr[node], end = ptr[node + 1];

    float2 acc = make_float2(0.f, 0.f);
    int k = beg;
    for (; k + 4 <= end; k += 4) {
        int s0 = csr[k], s1 = csr[k + 1], s2 = csr[k + 2], s3 = csr[k + 3];
        float c0 = dv[s0], c1 = dv[s1], c2 = dv[s2], c3 = dv[s3];
        float2 v0 = ((const float2*)g_hw)[s0 * 32 + lane];
        float2 v1 = ((const float2*)g_hw)[s1 * 32 + lane];
        float2 v2 = ((const float2*)g_hw)[s2 * 32 + lane];
        float2 v3 = ((const float2*)g_hw)[s3 * 32 + lane];
        acc.x += c0 * v0.x + c1 * v1.x + c2 * v2.x + c3 * v3.x;
        acc.y += c0 * v0.y + c1 * v1.y + c2 * v2.y + c3 * v3.y;
    }
    for (; k < end; k++) {
        int s = csr[k];
        float c = dv[s];
        float2 v = ((const float2*)g_hw)[s * 32 + lane];
        acc.x += c * v.x;
        acc.y += c * v.y;
    }

    float dd = dv[node];
    float2 bv = ((const float2*)bias)[lane];
    float2 o = make_float2(acc.x * dd + bv.x, acc.y * dd + bv.y);
    float ss  = warp_sum(o.x * o.x + o.y * o.y);
    float inv = 1.0f / fmaxf(sqrtf(ss), 1e-12f);
    float2 h = make_float2(o.x * inv, o.y * inv);
    if (write_h) ((float2*)g_h)[node * 32 + lane] = h;

    float* res = (res_sel < 0) ? g_base : g_beh[res_sel];
    float2 r = add_base ? ((const float2*)g_base)[node * 32 + lane]
                        : ((const float2*)res)[node * 32 + lane];
    ((float2*)res)[node * 32 + lane] = make_float2(r.x + h.x * invL, r.y + h.y * invL);
}

/* ---------------- mutual attention + weighted combine ---------------- */
__global__ void attn_k() {
    int t = blockIdx.x * blockDim.x + threadIdx.x;
    int node = t >> 5, lane = t & 31;
    if (node >= NND) return;
    int off = node * 32 + lane;
    float2 t0 = ((const float2*)g_beh[0])[off];
    float2 t1 = ((const float2*)g_beh[1])[off];
    float2 t2 = ((const float2*)g_beh[2])[off];

    float s00 = warp_sum(t0.x * t0.x + t0.y * t0.y);
    float s01 = warp_sum(t0.x * t1.x + t0.y * t1.y);
    float s02 = warp_sum(t0.x * t2.x + t0.y * t2.y);
    float s11 = warp_sum(t1.x * t1.x + t1.y * t1.y);
    float s12 = warp_sum(t1.x * t2.x + t1.y * t2.y);
    float s22 = warp_sum(t2.x * t2.x + t2.y * t2.y);

    const float sc = 0.125f;
    float s[3][3] = {{s00 * sc, s01 * sc, s02 * sc},
                     {s01 * sc, s11 * sc, s12 * sc},
                     {s02 * sc, s12 * sc, s22 * sc}};

    bool isU = node < NU;
    float gw = isU ? 2.35f : 1.0f;
    float bw = isU ? 0.242f : 0.55f;
    float2 gv = ((const float2*)g_base)[off];

#pragma unroll
    for (int b = 0; b < 3; b++) {
        float m  = fmaxf(s[b][0], fmaxf(s[b][1], s[b][2]));
        float e0 = __expf(s[b][0] - m), e1 = __expf(s[b][1] - m), e2 = __expf(s[b][2] - m);
        float is = 1.0f / (e0 + e1 + e2);
        float a0 = e0 * is, a1 = e1 * is, a2 = e2 * is;
        float2 o = make_float2(a0 * t0.x + a1 * t1.x + a2 * t2.x,
                               a0 * t0.y + a1 * t1.y + a2 * t2.y);
        ((float2*)g_w[b])[off] = make_float2(gw * gv.x + bw * o.x,
                                             gw * gv.y + bw * o.y);
    }
}

/* ---------------- BPR loss ---------------- */
__global__ void loss_k(const int* __restrict__ bd, float* out) {
    int t = blockIdx.x * blockDim.x + threadIdx.x;
    int w = t >> 5, lane = t & 31;
    float partial = 0.0f;
    if (w < BATCH * 9) {
        int k = w / 9, pr = w - k * 9;
        int i = pr / 3, j = pr - i * 3;
        int u   = bd[k * 9 + i * 3 + 0];
        int ip  = bd[k * 9 + i * 3 + 1];
        int in_ = bd[k * 9 + i * 3 + 2];
        float2 uu = ((const float2*)g_w[i])[u * 32 + lane];
        float2 pp = ((const float2*)g_w[j])[(NU + ip) * 32 + lane];
        float2 nn = ((const float2*)g_w[j])[(NU + in_) * 32 + lane];
        float sp = warp_sum(uu.x * pp.x + uu.y * pp.y);
        float sn = warp_sum(uu.x * nn.x + uu.y * nn.y);
        float x  = sp - sn;
        float ls = fminf(x, 0.0f) - log1pf(expf(-fabsf(x)));
        partial = -ls * (1.0f / (float)BATCH);
    }
    __shared__ float sm[8];
    if (lane == 0) sm[threadIdx.x >> 5] = partial;
    __syncthreads();
    if (threadIdx.x == 0) {
        float s = 0.0f;
#pragma unroll
        for (int q = 0; q < 8; q++) s += sm[q];
        atomicAdd(out, s);
    }
}

__global__ void final_k(float* out) {
    out[0] += 0.001f * ((sqrtf(g_sc[0]) + sqrtf(g_sc[1])) / (float)(N_ITEMS + 1));
}

/* ================================ launch ================================ */
extern "C" void kernel_launch(void* const* d_in, const int* in_sizes, int n_in,
                              void* d_out, int out_size) {
    const float* ue  = (const float*)d_in[0];
    const float* ie  = (const float*)d_in[1];
    const float* gW  = (const float*)d_in[2];
    const float* gb  = (const float*)d_in[3];
    const float* bW  = (const float*)d_in[4];
    const float* bb  = (const float*)d_in[5];
    const int*   aei = (const int*)d_in[6];
    const int*   bei = (const int*)d_in[7];
    const int*   bd  = (const int*)d_in[8];
    float* out = (float*)d_out;

    const int T = 256;
    dim3 blk(T);

    zero_k<<<(4 * NND + T - 1) / T, blk>>>(out);
    concat_k<<<(NND * 16 + T - 1) / T, blk>>>(ue, ie);
    sumsq_k<<<256, blk>>>(ue, NU * 16, 0);
    sumsq_k<<<256, blk>>>(ie, (N_ITEMS + 1) * 16, 1);

    /* degrees + dinv */
    degcnt_k<<<(E_GLOBAL + T - 1) / T, blk>>>(aei + E_GLOBAL, E_GLOBAL, 0);
    for (int b = 0; b < 3; b++)
        degcnt_k<<<(E_BEH + T - 1) / T, blk>>>(bei + (b * 2 + 1) * E_BEH, E_BEH, 1 + b);
    dinv_k<<<(4 * NND + T - 1) / T, blk>>>();

    /* CSR build */
    part_k<<<4 * NCH, SCB>>>();
    scanpart_k<<<1, 32>>>();
    scan_k<<<4 * NCH, SCB>>>();
    fill_k<<<(E_GLOBAL + T - 1) / T, blk>>>(aei, aei + E_GLOBAL, E_GLOBAL, 0, 0);
    for (int b = 0; b < 3; b++) {
        const int* bsrc = bei + b * 2 * E_BEH;
        fill_k<<<(E_BEH + T - 1) / T, blk>>>(bsrc, bsrc + E_BEH, E_BEH, 1 + b,
                                             E_GLOBAL + b * E_BEH);
    }

    const int GEMM_BLOCKS = (NND + 63) / 64;
    const int NODE_BLOCKS = (NND * 32 + T - 1) / T;

    /* global encoder: 2 layers */
    gemm_k<<<GEMM_BLOCKS, 128>>>(gW, 0);
    gather_k<<<NODE_BLOCKS, blk>>>(0, 0, gb, 1.0f, -1, 0, 1);
    gemm_k<<<GEMM_BLOCKS, 128>>>(gW + 4096, 1);
    gather_k<<<NODE_BLOCKS, blk>>>(0, 0, gb + 64, 0.5f, -1, 0, 0);

    /* behavioral encoders: 3 x 2 layers */
    for (int b = 0; b < 3; b++) {
        int cbase = E_GLOBAL + b * E_BEH;
        gemm_k<<<GEMM_BLOCKS, 128>>>(bW + (b * 2) * 4096, 0);
        gather_k<<<NODE_BLOCKS, blk>>>(cbase, 1 + b, bb + (b * 2) * 64, 1.0f, b, 1, 1);
        gemm_k<<<GEMM_BLOCKS, 128>>>(bW + (b * 2 + 1) * 4096, 1);
        gather_k<<<NODE_BLOCKS, blk>>>(cbase, 1 + b, bb + (b * 2 + 1) * 64, 0.5f, b, 0, 0);
    }

    attn_k<<<NODE_BLOCKS, blk>>>();
    loss_k<<<(BATCH * 9 * 32 + T - 1) / T, blk>>>(bd, out);
    final_k<<<1, 1>>>(out);
}